// round 1
// baseline (speedup 1.0000x reference)
#include <cuda_runtime.h>

// ---------------------------------------------------------------------------
// FrequencyAwareEmbedding: out[t] = table[bucket[x[t]]][x[t]]  (32 floats)
// where tables 3/4 are pre-projected (emb @ W + b) into device scratch.
//
// Inputs (metadata order):
//  0: x        int32   [512*2048]
//  1: bucket   int32   [100000]
//  2: emb0     f32     [100000,32]
//  3: emb1     f32     [100000,32]
//  4: emb2     f32     [100000,32]
//  5: emb3     f32     [100000,51]
//  6: emb4     f32     [100000,102]
//  7: W3       f32     [51,32]
//  8: b3       f32     [32]
//  9: W4       f32     [102,32]
// 10: b4       f32     [32]
// Output: f32 [512*2048*32]
// ---------------------------------------------------------------------------

#define NUM_EMB_MAX 100000

// Scratch for projected tables (allowed: __device__ globals, no allocation).
__device__ float g_proj3[NUM_EMB_MAX * 32];
__device__ float g_proj4[NUM_EMB_MAX * 32];

// One warp per table row; lane j computes output column j.
// Only rows actually assigned to `my_bucket` are projected (~1/5 of rows),
// cutting FMA work and emb3/emb4 read traffic by 5x.
__global__ void project_kernel(const float* __restrict__ emb,
                               const float* __restrict__ W,
                               const float* __restrict__ b,
                               const int*   __restrict__ bucket,
                               float*       __restrict__ out,
                               int rows, int K, int my_bucket)
{
    int row = blockIdx.x * (blockDim.x >> 5) + (threadIdx.x >> 5);
    if (row >= rows) return;
    if (bucket[row] != my_bucket) return;   // whole warp takes same path

    int j = threadIdx.x & 31;
    const float* e = emb + (long long)row * K;

    float acc = b[j];
    #pragma unroll 3
    for (int k = 0; k < K; ++k) {
        // e[k] is uniform across the warp (broadcast load); W row is coalesced.
        acc = fmaf(e[k], W[k * 32 + j], acc);
    }
    out[row * 32 + j] = acc;
}

// 8 threads per token; each thread moves one float4 (16B) of the 128B row.
__global__ void gather_kernel(const int*   __restrict__ x,
                              const int*   __restrict__ bucket,
                              const float* __restrict__ e0,
                              const float* __restrict__ e1,
                              const float* __restrict__ e2,
                              float4*      __restrict__ out,
                              int T)
{
    int gid   = blockIdx.x * blockDim.x + threadIdx.x;
    int token = gid >> 3;
    if (token >= T) return;
    int c = gid & 7;

    int idx = __ldg(&x[token]);
    int bk  = __ldg(&bucket[idx]);

    const float* tab;
    switch (bk) {
        case 0:  tab = e0;       break;
        case 1:  tab = e1;       break;
        case 2:  tab = e2;       break;
        case 3:  tab = g_proj3;  break;
        default: tab = g_proj4;  break;
    }

    const float4* src = reinterpret_cast<const float4*>(tab);
    out[(long long)token * 8 + c] = __ldg(&src[(long long)idx * 8 + c]);
}

extern "C" void kernel_launch(void* const* d_in, const int* in_sizes, int n_in,
                              void* d_out, int out_size)
{
    const int*   x      = (const int*)  d_in[0];
    const int*   bucket = (const int*)  d_in[1];
    const float* emb0   = (const float*)d_in[2];
    const float* emb1   = (const float*)d_in[3];
    const float* emb2   = (const float*)d_in[4];
    const float* emb3   = (const float*)d_in[5];
    const float* emb4   = (const float*)d_in[6];
    const float* W3     = (const float*)d_in[7];
    const float* b3     = (const float*)d_in[8];
    const float* W4     = (const float*)d_in[9];
    const float* b4     = (const float*)d_in[10];

    const int T    = in_sizes[0];              // 1,048,576 tokens
    const int rows = in_sizes[1];              // 100,000
    const int K3   = in_sizes[5] / rows;       // 51
    const int K4   = in_sizes[6] / rows;       // 102

    float* proj3;
    float* proj4;
    cudaGetSymbolAddress((void**)&proj3, g_proj3);
    cudaGetSymbolAddress((void**)&proj4, g_proj4);

    // --- Stage 1: project bucket-3 and bucket-4 rows into scratch tables ---
    const int WARPS_PER_BLOCK = 8;
    const int THREADS = WARPS_PER_BLOCK * 32;
    int proj_blocks = (rows + WARPS_PER_BLOCK - 1) / WARPS_PER_BLOCK;

    project_kernel<<<proj_blocks, THREADS>>>(emb3, W3, b3, bucket, proj3, rows, K3, 3);
    project_kernel<<<proj_blocks, THREADS>>>(emb4, W4, b4, bucket, proj4, rows, K4, 4);

    // --- Stage 2: uniform 128B gather per token ---
    long long total_threads = (long long)T * 8;
    int gthreads = 256;
    int gblocks  = (int)((total_threads + gthreads - 1) / gthreads);
    gather_kernel<<<gblocks, gthreads>>>(x, bucket, emb0, emb1, emb2,
                                         (float4*)d_out, T);
}

// round 2
// speedup vs baseline: 1.3736x; 1.3736x over previous
#include <cuda_runtime.h>

// ---------------------------------------------------------------------------
// FrequencyAwareEmbedding, round 2.
// Stage A: compact bucket-3/4 row ids (warp-aggregated atomics).
// Stage B: build ONE combined table g_all[100000][32]:
//          - buckets 0..2: copy row from emb0/1/2
//          - buckets 3,4 : project emb3@W3+b3 / emb4@W4+b4 (8 rows per warp,
//            W rows amortized 8x, e broadcast via shfl -> LSU-light)
// Stage C: gather out[t] = g_all[x[t]]   (single 2-deep load chain,
//          12.8MB table is L2-resident -> LTS/DRAM bound)
// ---------------------------------------------------------------------------

#define NROWS_MAX 100000
#define ODIM 32

__device__ __align__(256) float g_all[NROWS_MAX * ODIM];
__device__ int g_list3[NROWS_MAX];
__device__ int g_list4[NROWS_MAX];
__device__ int g_cnt[2];

__global__ void reset_kernel() { g_cnt[0] = 0; g_cnt[1] = 0; }

// One thread per row; warp-aggregated atomic append to the per-bucket lists.
__global__ void build_lists(const int* __restrict__ bucket, int rows)
{
    int r = blockIdx.x * blockDim.x + threadIdx.x;
    int bk = (r < rows) ? bucket[r] : -1;      // keep full warp active for ballot
    int lane = threadIdx.x & 31;

    #pragma unroll
    for (int b = 3; b <= 4; ++b) {
        unsigned m = __ballot_sync(0xffffffffu, bk == b);
        if (bk == b) {
            int leader = __ffs(m) - 1;
            int base = 0;
            if (lane == leader) base = atomicAdd(&g_cnt[b - 3], __popc(m));
            base = __shfl_sync(m, base, leader);
            int* list = (b == 3) ? g_list3 : g_list4;
            list[base + __popc(m & ((1u << lane) - 1u))] = r;
        }
    }
}

// Copy buckets 0..2 into g_all. 8 threads per row, float4 moves.
__global__ void copy_rows(const int*    __restrict__ bucket,
                          const float4* __restrict__ e0,
                          const float4* __restrict__ e1,
                          const float4* __restrict__ e2,
                          float4*       __restrict__ out,
                          int rows)
{
    int gid = blockIdx.x * blockDim.x + threadIdx.x;
    int r = gid >> 3;
    if (r >= rows) return;
    int c = gid & 7;

    int bk = __ldg(&bucket[r]);
    if (bk > 2) return;
    const float4* t = (bk == 0) ? e0 : ((bk == 1) ? e1 : e2);
    out[(size_t)r * 8 + c] = __ldg(&t[(size_t)r * 8 + c]);
}

// Project 8 same-bucket rows per warp. Lane j owns output column j.
// e rows live in registers (coalesced loads), broadcast per-k via shfl;
// each W row (128B, L1-hot) is loaded once per 8 rows.
template <int K>
__global__ void project_list(const float* __restrict__ emb,
                             const float* __restrict__ W,
                             const float* __restrict__ b,
                             const int*   __restrict__ list,
                             const int*   __restrict__ cnt_ptr,
                             float*       __restrict__ out)
{
    constexpr int CH = (K + 31) / 32;   // 32-wide e chunks per row
    const int cnt = *cnt_ptr;
    int wid  = blockIdx.x * (blockDim.x >> 5) + (threadIdx.x >> 5);
    int nw   = gridDim.x  * (blockDim.x >> 5);
    int lane = threadIdx.x & 31;

    float bias = b[lane];

    for (int base = wid * 8; base < cnt; base += nw * 8) {
        int nvalid = cnt - base;
        if (nvalid > 8) nvalid = 8;

        int rows[8];
        #pragma unroll
        for (int r = 0; r < 8; ++r)
            rows[r] = __ldg(&list[base + (r < nvalid ? r : 0)]);

        // Coalesced pull of e rows into registers.
        float ev[8][CH];
        #pragma unroll
        for (int r = 0; r < 8; ++r) {
            #pragma unroll
            for (int ch = 0; ch < CH; ++ch) {
                int k = ch * 32 + lane;
                ev[r][ch] = (k < K) ? __ldg(&emb[(size_t)rows[r] * K + k]) : 0.0f;
            }
        }

        float acc[8];
        #pragma unroll
        for (int r = 0; r < 8; ++r) acc[r] = bias;

        // k-loop: static ev chunk index (no local-mem spill), dynamic shfl src.
        #pragma unroll
        for (int ch = 0; ch < CH; ++ch) {
            const int kmax = (K - ch * 32 < 32) ? (K - ch * 32) : 32;
            #pragma unroll 8
            for (int src = 0; src < kmax; ++src) {
                float w = __ldg(&W[(ch * 32 + src) * 32 + lane]);
                #pragma unroll
                for (int r = 0; r < 8; ++r) {
                    float e = __shfl_sync(0xffffffffu, ev[r][ch], src);
                    acc[r] = fmaf(e, w, acc[r]);
                }
            }
        }

        #pragma unroll
        for (int r = 0; r < 8; ++r)
            if (r < nvalid)
                out[(size_t)rows[r] * ODIM + lane] = acc[r];
    }
}

// 8 threads per token; one float4 each from the combined table.
__global__ void gather_kernel(const int*    __restrict__ x,
                              const float4* __restrict__ tab,
                              float4*       __restrict__ out,
                              int T)
{
    int gid = blockIdx.x * blockDim.x + threadIdx.x;
    int token = gid >> 3;
    if (token >= T) return;
    int c = gid & 7;

    int idx = __ldg(&x[token]);
    out[(size_t)token * 8 + c] = __ldg(&tab[(size_t)idx * 8 + c]);
}

extern "C" void kernel_launch(void* const* d_in, const int* in_sizes, int n_in,
                              void* d_out, int out_size)
{
    const int*   x      = (const int*)  d_in[0];
    const int*   bucket = (const int*)  d_in[1];
    const float* emb0   = (const float*)d_in[2];
    const float* emb1   = (const float*)d_in[3];
    const float* emb2   = (const float*)d_in[4];
    const float* emb3   = (const float*)d_in[5];
    const float* W3     = (const float*)d_in[7];
    const float* b3     = (const float*)d_in[8];
    const float* emb4   = (const float*)d_in[6];
    const float* W4     = (const float*)d_in[9];
    const float* b4     = (const float*)d_in[10];

    const int T    = in_sizes[0];          // 1,048,576 tokens
    const int rows = in_sizes[1];          // 100,000

    float* all_f;
    int*   list3;
    int*   list4;
    int*   cnt;
    cudaGetSymbolAddress((void**)&all_f, g_all);
    cudaGetSymbolAddress((void**)&list3, g_list3);
    cudaGetSymbolAddress((void**)&list4, g_list4);
    cudaGetSymbolAddress((void**)&cnt,   g_cnt);

    reset_kernel<<<1, 1>>>();

    build_lists<<<(rows + 255) / 256, 256>>>(bucket, rows);

    copy_rows<<<(rows * 8 + 255) / 256, 256>>>(
        bucket, (const float4*)emb0, (const float4*)emb1, (const float4*)emb2,
        (float4*)all_f, rows);

    // ~2500 warp-groups of 8 rows each per bucket -> 320 blocks x 8 warps.
    project_list<51> <<<320, 256>>>(emb3, W3, b3, list3, cnt + 0, all_f);
    project_list<102><<<320, 256>>>(emb4, W4, b4, list4, cnt + 1, all_f);

    long long gthreads_total = (long long)T * 8;
    int gblocks = (int)((gthreads_total + 255) / 256);
    gather_kernel<<<gblocks, 256>>>(x, (const float4*)all_f, (float4*)d_out, T);
}

// round 3
// speedup vs baseline: 1.8204x; 1.3253x over previous
#include <cuda_runtime.h>

// ---------------------------------------------------------------------------
// FrequencyAwareEmbedding, round 3.
//  reset -> build_lists -> stage_b (fused copy + proj51 + proj102) -> gather
//
// stage_b block roles (proj first: it's the latency-bound long pole):
//   [0,              NB51)                 : project bucket-3 rows (emb3@W3+b3)
//   [NB51,           NB51+NB102)           : project bucket-4 rows (emb4@W4+b4)
//   [NB51+NB102,     NB51+NB102+NBCOPY)    : copy bucket-0..2 rows
// ---------------------------------------------------------------------------

#define NROWS_MAX 100000
#define ODIM 32

__device__ __align__(256) float g_all[NROWS_MAX * ODIM];
__device__ int g_list3[NROWS_MAX];
__device__ int g_list4[NROWS_MAX];
__device__ int g_cnt[2];

__global__ void reset_kernel() { g_cnt[0] = 0; g_cnt[1] = 0; }

// One thread per row; warp-aggregated atomic append to per-bucket lists.
__global__ void build_lists(const int* __restrict__ bucket, int rows)
{
    int r = blockIdx.x * blockDim.x + threadIdx.x;
    int bk = (r < rows) ? bucket[r] : -1;
    int lane = threadIdx.x & 31;

    #pragma unroll
    for (int b = 3; b <= 4; ++b) {
        unsigned m = __ballot_sync(0xffffffffu, bk == b);
        if (bk == b) {
            int leader = __ffs(m) - 1;
            int base = 0;
            if (lane == leader) base = atomicAdd(&g_cnt[b - 3], __popc(m));
            base = __shfl_sync(m, base, leader);
            int* list = (b == 3) ? g_list3 : g_list4;
            list[base + __popc(m & ((1u << lane) - 1u))] = r;
        }
    }
}

// Project 8 same-bucket rows per warp (lane j = output col j).
template <int K>
__device__ __forceinline__ void project_impl(const float* __restrict__ emb,
                                             const float* __restrict__ W,
                                             const float* __restrict__ b,
                                             const int*   __restrict__ list,
                                             const int*   __restrict__ cnt_ptr,
                                             float*       __restrict__ out,
                                             int wid, int nw)
{
    constexpr int CH = (K + 31) / 32;
    const int cnt = *cnt_ptr;
    int lane = threadIdx.x & 31;

    float bias = b[lane];

    for (int base = wid * 8; base < cnt; base += nw * 8) {
        int nvalid = cnt - base;
        if (nvalid > 8) nvalid = 8;

        int rows[8];
        #pragma unroll
        for (int r = 0; r < 8; ++r)
            rows[r] = __ldg(&list[base + (r < nvalid ? r : 0)]);

        float ev[8][CH];
        #pragma unroll
        for (int r = 0; r < 8; ++r) {
            #pragma unroll
            for (int ch = 0; ch < CH; ++ch) {
                int k = ch * 32 + lane;
                ev[r][ch] = (k < K) ? __ldg(&emb[(size_t)rows[r] * K + k]) : 0.0f;
            }
        }

        float acc[8];
        #pragma unroll
        for (int r = 0; r < 8; ++r) acc[r] = bias;

        #pragma unroll
        for (int ch = 0; ch < CH; ++ch) {
            const int kmax = (K - ch * 32 < 32) ? (K - ch * 32) : 32;
            #pragma unroll 8
            for (int src = 0; src < kmax; ++src) {
                float w = __ldg(&W[(ch * 32 + src) * 32 + lane]);
                #pragma unroll
                for (int r = 0; r < 8; ++r) {
                    float e = __shfl_sync(0xffffffffu, ev[r][ch], src);
                    acc[r] = fmaf(e, w, acc[r]);
                }
            }
        }

        #pragma unroll
        for (int r = 0; r < 8; ++r)
            if (r < nvalid)
                out[(size_t)rows[r] * ODIM + lane] = acc[r];
    }
}

// Copy one 32-row tile of buckets 0..2 (8 threads/row, float4 moves).
__device__ __forceinline__ void copy_impl(const int*    __restrict__ bucket,
                                          const float4* __restrict__ e0,
                                          const float4* __restrict__ e1,
                                          const float4* __restrict__ e2,
                                          float4*       __restrict__ out,
                                          int rows, int tile)
{
    int gid = tile * 256 + threadIdx.x;
    int r = gid >> 3;
    if (r >= rows) return;
    int c = gid & 7;

    int bk = __ldg(&bucket[r]);
    if (bk > 2) return;
    const float4* t = (bk == 0) ? e0 : ((bk == 1) ? e1 : e2);
    out[(size_t)r * 8 + c] = __ldg(&t[(size_t)r * 8 + c]);
}

__global__ void stage_b(const int*    __restrict__ bucket,
                        const float4* __restrict__ e0,
                        const float4* __restrict__ e1,
                        const float4* __restrict__ e2,
                        const float*  __restrict__ emb3,
                        const float*  __restrict__ W3,
                        const float*  __restrict__ b3,
                        const float*  __restrict__ emb4,
                        const float*  __restrict__ W4,
                        const float*  __restrict__ b4,
                        float*        __restrict__ all_f,
                        int rows, int nb51, int nb102)
{
    int warp_in_block = threadIdx.x >> 5;

    if (blockIdx.x < (unsigned)nb51) {
        int wid = blockIdx.x * 8 + warp_in_block;
        project_impl<51>(emb3, W3, b3, g_list3, &g_cnt[0], all_f,
                         wid, nb51 * 8);
    } else if (blockIdx.x < (unsigned)(nb51 + nb102)) {
        int wid = (blockIdx.x - nb51) * 8 + warp_in_block;
        project_impl<102>(emb4, W4, b4, g_list4, &g_cnt[1], all_f,
                          wid, nb102 * 8);
    } else {
        int tile = blockIdx.x - nb51 - nb102;
        copy_impl(bucket, e0, e1, e2, (float4*)all_f, rows, tile);
    }
}

// 8 threads per token; one float4 each from the combined table.
// Stores use evict-first hint so the 128MB output stream doesn't evict the
// L2-resident 12.8MB table.
__global__ void gather_kernel(const int*    __restrict__ x,
                              const float4* __restrict__ tab,
                              float4*       __restrict__ out,
                              int T)
{
    int gid = blockIdx.x * blockDim.x + threadIdx.x;
    int token = gid >> 3;
    if (token >= T) return;
    int c = gid & 7;

    int idx = __ldg(&x[token]);
    float4 v = __ldg(&tab[(size_t)idx * 8 + c]);
    __stcs(&out[(size_t)token * 8 + c], v);
}

extern "C" void kernel_launch(void* const* d_in, const int* in_sizes, int n_in,
                              void* d_out, int out_size)
{
    const int*   x      = (const int*)  d_in[0];
    const int*   bucket = (const int*)  d_in[1];
    const float* emb0   = (const float*)d_in[2];
    const float* emb1   = (const float*)d_in[3];
    const float* emb2   = (const float*)d_in[4];
    const float* emb3   = (const float*)d_in[5];
    const float* emb4   = (const float*)d_in[6];
    const float* W3     = (const float*)d_in[7];
    const float* b3     = (const float*)d_in[8];
    const float* W4     = (const float*)d_in[9];
    const float* b4     = (const float*)d_in[10];

    const int T    = in_sizes[0];          // 1,048,576 tokens
    const int rows = in_sizes[1];          // 100,000

    float* all_f;
    cudaGetSymbolAddress((void**)&all_f, g_all);

    reset_kernel<<<1, 1>>>();
    build_lists<<<(rows + 255) / 256, 256>>>(bucket, rows);

    const int NB51   = 320;                       // ~2500 groups of 8 rows
    const int NB102  = 320;
    const int NBCOPY = (rows * 8 + 255) / 256;    // 3125
    stage_b<<<NB51 + NB102 + NBCOPY, 256>>>(
        bucket, (const float4*)emb0, (const float4*)emb1, (const float4*)emb2,
        emb3, W3, b3, emb4, W4, b4, all_f, rows, NB51, NB102);

    long long gthreads_total = (long long)T * 8;
    int gblocks = (int)((gthreads_total + 255) / 256);
    gather_kernel<<<gblocks, 256>>>(x, (const float4*)all_f, (float4*)d_out, T);
}

// round 4
// speedup vs baseline: 2.1066x; 1.1572x over previous
#include <cuda_runtime.h>

// ---------------------------------------------------------------------------
// FrequencyAwareEmbedding, round 4.
//  build_lists -> stage_b (fused copy + proj51 + proj102) -> gather
//  (counter reset folded into gather; 4 tokens per 8-thread group in gather
//   for 4x memory-level parallelism)
// ---------------------------------------------------------------------------

#define NROWS_MAX 100000
#define ODIM 32

__device__ __align__(256) float g_all[NROWS_MAX * ODIM];
__device__ int g_list3[NROWS_MAX];
__device__ int g_list4[NROWS_MAX];
__device__ int g_cnt[2];   // zero-initialized at load; re-zeroed by gather

// One thread per row; warp-aggregated atomic append to per-bucket lists.
__global__ void build_lists(const int* __restrict__ bucket, int rows)
{
    int r = blockIdx.x * blockDim.x + threadIdx.x;
    int bk = (r < rows) ? bucket[r] : -1;
    int lane = threadIdx.x & 31;

    #pragma unroll
    for (int b = 3; b <= 4; ++b) {
        unsigned m = __ballot_sync(0xffffffffu, bk == b);
        if (bk == b) {
            int leader = __ffs(m) - 1;
            int base = 0;
            if (lane == leader) base = atomicAdd(&g_cnt[b - 3], __popc(m));
            base = __shfl_sync(m, base, leader);
            int* list = (b == 3) ? g_list3 : g_list4;
            list[base + __popc(m & ((1u << lane) - 1u))] = r;
        }
    }
}

// Project 8 same-bucket rows per warp (lane j = output col j).
template <int K>
__device__ __forceinline__ void project_impl(const float* __restrict__ emb,
                                             const float* __restrict__ W,
                                             const float* __restrict__ b,
                                             const int*   __restrict__ list,
                                             const int*   __restrict__ cnt_ptr,
                                             float*       __restrict__ out,
                                             int wid, int nw)
{
    constexpr int CH = (K + 31) / 32;
    const int cnt = *cnt_ptr;
    int lane = threadIdx.x & 31;

    float bias = b[lane];

    for (int base = wid * 8; base < cnt; base += nw * 8) {
        int nvalid = cnt - base;
        if (nvalid > 8) nvalid = 8;

        int rows[8];
        #pragma unroll
        for (int r = 0; r < 8; ++r)
            rows[r] = __ldg(&list[base + (r < nvalid ? r : 0)]);

        float ev[8][CH];
        #pragma unroll
        for (int r = 0; r < 8; ++r) {
            #pragma unroll
            for (int ch = 0; ch < CH; ++ch) {
                int k = ch * 32 + lane;
                ev[r][ch] = (k < K) ? __ldg(&emb[(size_t)rows[r] * K + k]) : 0.0f;
            }
        }

        float acc[8];
        #pragma unroll
        for (int r = 0; r < 8; ++r) acc[r] = bias;

        #pragma unroll
        for (int ch = 0; ch < CH; ++ch) {
            const int kmax = (K - ch * 32 < 32) ? (K - ch * 32) : 32;
            #pragma unroll 8
            for (int src = 0; src < kmax; ++src) {
                float w = __ldg(&W[(ch * 32 + src) * 32 + lane]);
                #pragma unroll
                for (int r = 0; r < 8; ++r) {
                    float e = __shfl_sync(0xffffffffu, ev[r][ch], src);
                    acc[r] = fmaf(e, w, acc[r]);
                }
            }
        }

        #pragma unroll
        for (int r = 0; r < 8; ++r)
            if (r < nvalid)
                out[(size_t)rows[r] * ODIM + lane] = acc[r];
    }
}

// Copy one 32-row tile of buckets 0..2 (8 threads/row, float4 moves).
__device__ __forceinline__ void copy_impl(const int*    __restrict__ bucket,
                                          const float4* __restrict__ e0,
                                          const float4* __restrict__ e1,
                                          const float4* __restrict__ e2,
                                          float4*       __restrict__ out,
                                          int rows, int tile)
{
    int gid = tile * 256 + threadIdx.x;
    int r = gid >> 3;
    if (r >= rows) return;
    int c = gid & 7;

    int bk = __ldg(&bucket[r]);
    if (bk > 2) return;
    const float4* t = (bk == 0) ? e0 : ((bk == 1) ? e1 : e2);
    out[(size_t)r * 8 + c] = __ldg(&t[(size_t)r * 8 + c]);
}

__global__ void stage_b(const int*    __restrict__ bucket,
                        const float4* __restrict__ e0,
                        const float4* __restrict__ e1,
                        const float4* __restrict__ e2,
                        const float*  __restrict__ emb3,
                        const float*  __restrict__ W3,
                        const float*  __restrict__ b3,
                        const float*  __restrict__ emb4,
                        const float*  __restrict__ W4,
                        const float*  __restrict__ b4,
                        float*        __restrict__ all_f,
                        int rows, int nb51, int nb102)
{
    int warp_in_block = threadIdx.x >> 5;

    if (blockIdx.x < (unsigned)nb51) {
        int wid = blockIdx.x * 8 + warp_in_block;
        project_impl<51>(emb3, W3, b3, g_list3, &g_cnt[0], all_f,
                         wid, nb51 * 8);
    } else if (blockIdx.x < (unsigned)(nb51 + nb102)) {
        int wid = (blockIdx.x - nb51) * 8 + warp_in_block;
        project_impl<102>(emb4, W4, b4, g_list4, &g_cnt[1], all_f,
                          wid, nb102 * 8);
    } else {
        int tile = blockIdx.x - nb51 - nb102;
        copy_impl(bucket, e0, e1, e2, (float4*)all_f, rows, tile);
    }
}

// 8-thread group handles FOUR tokens: one broadcast int4 idx load, then four
// independent 16B table loads in flight (MLP=4), then four 16B stores.
// Also re-zeroes the list counters for the next graph replay (no reader of
// g_cnt exists in this kernel; stream order publishes it to next build_lists).
__global__ void gather_kernel(const int4*   __restrict__ x4,
                              const float4* __restrict__ tab,
                              float4*       __restrict__ out,
                              int Tg)
{
    if (blockIdx.x == 0 && threadIdx.x == 0) { g_cnt[0] = 0; g_cnt[1] = 0; }

    int gid = blockIdx.x * blockDim.x + threadIdx.x;
    int grp = gid >> 3;          // group of 4 tokens
    if (grp >= Tg) return;
    int c = gid & 7;

    int4 idx = __ldg(&x4[grp]);

    float4 v0 = __ldg(&tab[(size_t)idx.x * 8 + c]);
    float4 v1 = __ldg(&tab[(size_t)idx.y * 8 + c]);
    float4 v2 = __ldg(&tab[(size_t)idx.z * 8 + c]);
    float4 v3 = __ldg(&tab[(size_t)idx.w * 8 + c]);

    size_t base = (size_t)grp * 32 + c;
    __stcs(&out[base +  0], v0);
    __stcs(&out[base +  8], v1);
    __stcs(&out[base + 16], v2);
    __stcs(&out[base + 24], v3);
}

extern "C" void kernel_launch(void* const* d_in, const int* in_sizes, int n_in,
                              void* d_out, int out_size)
{
    const int*   x      = (const int*)  d_in[0];
    const int*   bucket = (const int*)  d_in[1];
    const float* emb0   = (const float*)d_in[2];
    const float* emb1   = (const float*)d_in[3];
    const float* emb2   = (const float*)d_in[4];
    const float* emb3   = (const float*)d_in[5];
    const float* emb4   = (const float*)d_in[6];
    const float* W3     = (const float*)d_in[7];
    const float* b3     = (const float*)d_in[8];
    const float* W4     = (const float*)d_in[9];
    const float* b4     = (const float*)d_in[10];

    const int T    = in_sizes[0];          // 1,048,576 tokens (multiple of 4)
    const int rows = in_sizes[1];          // 100,000

    float* all_f;
    cudaGetSymbolAddress((void**)&all_f, g_all);

    build_lists<<<(rows + 255) / 256, 256>>>(bucket, rows);

    const int NB51   = 320;
    const int NB102  = 320;
    const int NBCOPY = (rows * 8 + 255) / 256;
    stage_b<<<NB51 + NB102 + NBCOPY, 256>>>(
        bucket, (const float4*)emb0, (const float4*)emb1, (const float4*)emb2,
        emb3, W3, b3, emb4, W4, b4, all_f, rows, NB51, NB102);

    const int Tg = T / 4;                        // token groups
    long long gthreads_total = (long long)Tg * 8;
    int gblocks = (int)((gthreads_total + 255) / 256);
    gather_kernel<<<gblocks, 256>>>((const int4*)x, (const float4*)all_f,
                                    (float4*)d_out, Tg);
}

// round 5
// speedup vs baseline: 2.1901x; 1.0396x over previous
#include <cuda_runtime.h>

// ---------------------------------------------------------------------------
// FrequencyAwareEmbedding, round 5.
//  build_lists (block-aggregated atomics) -> stage_b (fused copy+proj) -> gather
//  gather: 8 tokens per 8-thread group (MLP=8), resets list counters for the
//  next replay.
// ---------------------------------------------------------------------------

#define NROWS_MAX 100000
#define ODIM 32

__device__ __align__(256) float g_all[NROWS_MAX * ODIM];
__device__ int g_list3[NROWS_MAX];
__device__ int g_list4[NROWS_MAX];
__device__ int g_cnt[2];   // zero-initialized at load; re-zeroed by gather

// Block-aggregated list build: ONE atomicAdd per bucket per block.
__global__ void build_lists(const int* __restrict__ bucket, int rows)
{
    __shared__ int woff3[8], woff4[8];
    __shared__ int base3, base4;

    int r = blockIdx.x * blockDim.x + threadIdx.x;
    int bk = (r < rows) ? __ldg(&bucket[r]) : -1;
    int lane = threadIdx.x & 31;
    int wid  = threadIdx.x >> 5;

    unsigned m3 = __ballot_sync(0xffffffffu, bk == 3);
    unsigned m4 = __ballot_sync(0xffffffffu, bk == 4);

    if (lane == 0) { woff3[wid] = __popc(m3); woff4[wid] = __popc(m4); }
    __syncthreads();

    if (threadIdx.x == 0) {
        int t3 = 0, t4 = 0;
        #pragma unroll
        for (int i = 0; i < 8; ++i) {
            int c3 = woff3[i]; woff3[i] = t3; t3 += c3;
            int c4 = woff4[i]; woff4[i] = t4; t4 += c4;
        }
        base3 = (t3 > 0) ? atomicAdd(&g_cnt[0], t3) : 0;
        base4 = (t4 > 0) ? atomicAdd(&g_cnt[1], t4) : 0;
    }
    __syncthreads();

    unsigned lt = (1u << lane) - 1u;
    if (bk == 3) g_list3[base3 + woff3[wid] + __popc(m3 & lt)] = r;
    if (bk == 4) g_list4[base4 + woff4[wid] + __popc(m4 & lt)] = r;
}

// Project 8 same-bucket rows per warp (lane j = output col j).
template <int K>
__device__ __forceinline__ void project_impl(const float* __restrict__ emb,
                                             const float* __restrict__ W,
                                             const float* __restrict__ b,
                                             const int*   __restrict__ list,
                                             const int*   __restrict__ cnt_ptr,
                                             float*       __restrict__ out,
                                             int wid, int nw)
{
    constexpr int CH = (K + 31) / 32;
    const int cnt = *cnt_ptr;
    int lane = threadIdx.x & 31;

    float bias = b[lane];

    for (int base = wid * 8; base < cnt; base += nw * 8) {
        int nvalid = cnt - base;
        if (nvalid > 8) nvalid = 8;

        int rows[8];
        #pragma unroll
        for (int r = 0; r < 8; ++r)
            rows[r] = __ldg(&list[base + (r < nvalid ? r : 0)]);

        float ev[8][CH];
        #pragma unroll
        for (int r = 0; r < 8; ++r) {
            #pragma unroll
            for (int ch = 0; ch < CH; ++ch) {
                int k = ch * 32 + lane;
                ev[r][ch] = (k < K) ? __ldg(&emb[(size_t)rows[r] * K + k]) : 0.0f;
            }
        }

        float acc[8];
        #pragma unroll
        for (int r = 0; r < 8; ++r) acc[r] = bias;

        #pragma unroll
        for (int ch = 0; ch < CH; ++ch) {
            const int kmax = (K - ch * 32 < 32) ? (K - ch * 32) : 32;
            #pragma unroll 8
            for (int src = 0; src < kmax; ++src) {
                float w = __ldg(&W[(ch * 32 + src) * 32 + lane]);
                #pragma unroll
                for (int r = 0; r < 8; ++r) {
                    float e = __shfl_sync(0xffffffffu, ev[r][ch], src);
                    acc[r] = fmaf(e, w, acc[r]);
                }
            }
        }

        #pragma unroll
        for (int r = 0; r < 8; ++r)
            if (r < nvalid)
                out[(size_t)rows[r] * ODIM + lane] = acc[r];
    }
}

// Copy one 32-row tile of buckets 0..2 (8 threads/row, float4 moves).
__device__ __forceinline__ void copy_impl(const int*    __restrict__ bucket,
                                          const float4* __restrict__ e0,
                                          const float4* __restrict__ e1,
                                          const float4* __restrict__ e2,
                                          float4*       __restrict__ out,
                                          int rows, int tile)
{
    int gid = tile * 256 + threadIdx.x;
    int r = gid >> 3;
    if (r >= rows) return;
    int c = gid & 7;

    int bk = __ldg(&bucket[r]);
    if (bk > 2) return;
    const float4* t = (bk == 0) ? e0 : ((bk == 1) ? e1 : e2);
    out[(size_t)r * 8 + c] = __ldg(&t[(size_t)r * 8 + c]);
}

__global__ void stage_b(const int*    __restrict__ bucket,
                        const float4* __restrict__ e0,
                        const float4* __restrict__ e1,
                        const float4* __restrict__ e2,
                        const float*  __restrict__ emb3,
                        const float*  __restrict__ W3,
                        const float*  __restrict__ b3,
                        const float*  __restrict__ emb4,
                        const float*  __restrict__ W4,
                        const float*  __restrict__ b4,
                        float*        __restrict__ all_f,
                        int rows, int nb51, int nb102)
{
    int warp_in_block = threadIdx.x >> 5;

    if (blockIdx.x < (unsigned)nb51) {
        int wid = blockIdx.x * 8 + warp_in_block;
        project_impl<51>(emb3, W3, b3, g_list3, &g_cnt[0], all_f,
                         wid, nb51 * 8);
    } else if (blockIdx.x < (unsigned)(nb51 + nb102)) {
        int wid = (blockIdx.x - nb51) * 8 + warp_in_block;
        project_impl<102>(emb4, W4, b4, g_list4, &g_cnt[1], all_f,
                          wid, nb102 * 8);
    } else {
        int tile = blockIdx.x - nb51 - nb102;
        copy_impl(bucket, e0, e1, e2, (float4*)all_f, rows, tile);
    }
}

// 8-thread group handles EIGHT tokens: two int4 idx loads (broadcast), then
// eight independent 16B table loads in flight (MLP=8), then eight 16B stores.
// Also re-zeroes the list counters for the next graph replay.
__global__ void gather_kernel(const int4*   __restrict__ x4,
                              const float4* __restrict__ tab,
                              float4*       __restrict__ out,
                              int Tg)
{
    if (blockIdx.x == 0 && threadIdx.x == 0) { g_cnt[0] = 0; g_cnt[1] = 0; }

    int gid = blockIdx.x * blockDim.x + threadIdx.x;
    int grp = gid >> 3;          // group of 8 tokens
    if (grp >= Tg) return;
    int c = gid & 7;

    int4 ia = __ldg(&x4[(size_t)grp * 2 + 0]);
    int4 ib = __ldg(&x4[(size_t)grp * 2 + 1]);

    float4 v0 = __ldg(&tab[(size_t)ia.x * 8 + c]);
    float4 v1 = __ldg(&tab[(size_t)ia.y * 8 + c]);
    float4 v2 = __ldg(&tab[(size_t)ia.z * 8 + c]);
    float4 v3 = __ldg(&tab[(size_t)ia.w * 8 + c]);
    float4 v4 = __ldg(&tab[(size_t)ib.x * 8 + c]);
    float4 v5 = __ldg(&tab[(size_t)ib.y * 8 + c]);
    float4 v6 = __ldg(&tab[(size_t)ib.z * 8 + c]);
    float4 v7 = __ldg(&tab[(size_t)ib.w * 8 + c]);

    size_t base = (size_t)grp * 64 + c;
    __stcs(&out[base +  0], v0);
    __stcs(&out[base +  8], v1);
    __stcs(&out[base + 16], v2);
    __stcs(&out[base + 24], v3);
    __stcs(&out[base + 32], v4);
    __stcs(&out[base + 40], v5);
    __stcs(&out[base + 48], v6);
    __stcs(&out[base + 56], v7);
}

extern "C" void kernel_launch(void* const* d_in, const int* in_sizes, int n_in,
                              void* d_out, int out_size)
{
    const int*   x      = (const int*)  d_in[0];
    const int*   bucket = (const int*)  d_in[1];
    const float* emb0   = (const float*)d_in[2];
    const float* emb1   = (const float*)d_in[3];
    const float* emb2   = (const float*)d_in[4];
    const float* emb3   = (const float*)d_in[5];
    const float* emb4   = (const float*)d_in[6];
    const float* W3     = (const float*)d_in[7];
    const float* b3     = (const float*)d_in[8];
    const float* W4     = (const float*)d_in[9];
    const float* b4     = (const float*)d_in[10];

    const int T    = in_sizes[0];          // 1,048,576 tokens (multiple of 8)
    const int rows = in_sizes[1];          // 100,000

    float* all_f;
    cudaGetSymbolAddress((void**)&all_f, g_all);

    build_lists<<<(rows + 255) / 256, 256>>>(bucket, rows);

    const int NB51   = 320;
    const int NB102  = 320;
    const int NBCOPY = (rows * 8 + 255) / 256;
    stage_b<<<NB51 + NB102 + NBCOPY, 256>>>(
        bucket, (const float4*)emb0, (const float4*)emb1, (const float4*)emb2,
        emb3, W3, b3, emb4, W4, b4, all_f, rows, NB51, NB102);

    const int Tg = T / 8;                        // token groups of 8
    long long gthreads_total = (long long)Tg * 8;
    int gblocks = (int)((gthreads_total + 255) / 256);
    gather_kernel<<<gblocks, 256>>>((const int4*)x, (const float4*)all_f,
                                    (float4*)d_out, Tg);
}

// round 6
// speedup vs baseline: 2.2037x; 1.0062x over previous
#include <cuda_runtime.h>

// ---------------------------------------------------------------------------
// FrequencyAwareEmbedding, round 6.  TWO launches:
//   stage_b : blocks [0,391)   build bucket-3/4 row lists (tile = bid),
//             then in-kernel barrier, then project (131 blocks -> emb3@W3+b3,
//             260 blocks -> emb4@W4+b4) into the combined table.
//             blocks [391, ...) copy bucket-0..2 rows (overlaps build+proj).
//   gather  : out[t] = g_all[x[t]], 8 tokens / 8-thread group (MLP=8);
//             resets counters for next graph replay.
// ---------------------------------------------------------------------------

#define NROWS_MAX 100000
#define ODIM 32

#define NBUILD 391          // ceil(100000/256)
#define NB51   131          // build blocks that then project bucket 3
                            // remaining 260 project bucket 4

__device__ __align__(256) float g_all[NROWS_MAX * ODIM];
__device__ int g_list3[NROWS_MAX];
__device__ int g_list4[NROWS_MAX];
__device__ int g_cnt[2];        // zero-init at load; re-zeroed by gather
__device__ int g_build_done;    // idem

// --- build one 256-row tile of the bucket-3/4 lists (block-aggregated) ---
__device__ __forceinline__ void build_tile(const int* __restrict__ bucket,
                                           int rows, int tile)
{
    __shared__ int woff3[8], woff4[8];
    __shared__ int base3, base4;

    int r = tile * 256 + threadIdx.x;
    int bk = (r < rows) ? __ldg(&bucket[r]) : -1;
    int lane = threadIdx.x & 31;
    int wid  = threadIdx.x >> 5;

    unsigned m3 = __ballot_sync(0xffffffffu, bk == 3);
    unsigned m4 = __ballot_sync(0xffffffffu, bk == 4);

    if (lane == 0) { woff3[wid] = __popc(m3); woff4[wid] = __popc(m4); }
    __syncthreads();

    if (threadIdx.x == 0) {
        int t3 = 0, t4 = 0;
        #pragma unroll
        for (int i = 0; i < 8; ++i) {
            int c3 = woff3[i]; woff3[i] = t3; t3 += c3;
            int c4 = woff4[i]; woff4[i] = t4; t4 += c4;
        }
        base3 = (t3 > 0) ? atomicAdd(&g_cnt[0], t3) : 0;
        base4 = (t4 > 0) ? atomicAdd(&g_cnt[1], t4) : 0;
    }
    __syncthreads();

    unsigned lt = (1u << lane) - 1u;
    if (bk == 3) g_list3[base3 + woff3[wid] + __popc(m3 & lt)] = r;
    if (bk == 4) g_list4[base4 + woff4[wid] + __popc(m4 & lt)] = r;
}

// --- project 8 same-bucket rows per warp (lane j = output col j) ---
template <int K>
__device__ __forceinline__ void project_impl(const float* __restrict__ emb,
                                             const float* __restrict__ W,
                                             const float* __restrict__ b,
                                             const int*   __restrict__ list,
                                             int cnt,
                                             float*       __restrict__ out,
                                             int wid, int nw)
{
    constexpr int CH = (K + 31) / 32;
    int lane = threadIdx.x & 31;

    float bias = b[lane];

    for (int base = wid * 8; base < cnt; base += nw * 8) {
        int nvalid = cnt - base;
        if (nvalid > 8) nvalid = 8;

        int rows[8];
        #pragma unroll
        for (int r = 0; r < 8; ++r)
            rows[r] = __ldg(&list[base + (r < nvalid ? r : 0)]);

        float ev[8][CH];
        #pragma unroll
        for (int r = 0; r < 8; ++r) {
            #pragma unroll
            for (int ch = 0; ch < CH; ++ch) {
                int k = ch * 32 + lane;
                ev[r][ch] = (k < K) ? __ldg(&emb[(size_t)rows[r] * K + k]) : 0.0f;
            }
        }

        float acc[8];
        #pragma unroll
        for (int r = 0; r < 8; ++r) acc[r] = bias;

        #pragma unroll
        for (int ch = 0; ch < CH; ++ch) {
            const int kmax = (K - ch * 32 < 32) ? (K - ch * 32) : 32;
            #pragma unroll 8
            for (int src = 0; src < kmax; ++src) {
                float w = __ldg(&W[(ch * 32 + src) * 32 + lane]);
                #pragma unroll
                for (int r = 0; r < 8; ++r) {
                    float e = __shfl_sync(0xffffffffu, ev[r][ch], src);
                    acc[r] = fmaf(e, w, acc[r]);
                }
            }
        }

        #pragma unroll
        for (int r = 0; r < 8; ++r)
            if (r < nvalid)
                out[(size_t)rows[r] * ODIM + lane] = acc[r];
    }
}

// --- copy one 32-row tile of buckets 0..2 (8 threads/row, float4) ---
__device__ __forceinline__ void copy_impl(const int*    __restrict__ bucket,
                                          const float4* __restrict__ e0,
                                          const float4* __restrict__ e1,
                                          const float4* __restrict__ e2,
                                          float4*       __restrict__ out,
                                          int rows, int tile)
{
    int gid = tile * 256 + threadIdx.x;
    int r = gid >> 3;
    if (r >= rows) return;
    int c = gid & 7;

    int bk = __ldg(&bucket[r]);
    if (bk > 2) return;
    const float4* t = (bk == 0) ? e0 : ((bk == 1) ? e1 : e2);
    out[(size_t)r * 8 + c] = __ldg(&t[(size_t)r * 8 + c]);
}

__global__ void stage_b(const int*    __restrict__ bucket,
                        const float4* __restrict__ e0,
                        const float4* __restrict__ e1,
                        const float4* __restrict__ e2,
                        const float*  __restrict__ emb3,
                        const float*  __restrict__ W3,
                        const float*  __restrict__ b3,
                        const float*  __restrict__ emb4,
                        const float*  __restrict__ W4,
                        const float*  __restrict__ b4,
                        float*        __restrict__ all_f,
                        int rows)
{
    if (blockIdx.x < NBUILD) {
        // ---- build phase ----
        build_tile(bucket, rows, blockIdx.x);

        __threadfence();
        __syncthreads();
        if (threadIdx.x == 0) {
            atomicAdd(&g_build_done, 1);
            // spin until every build block has published its list entries
            while (atomicAdd(&g_build_done, 0) < NBUILD) { }
        }
        __syncthreads();
        __threadfence();

        // ---- projection phase (same blocks) ----
        int warp = threadIdx.x >> 5;
        if (blockIdx.x < NB51) {
            int wid = blockIdx.x * 8 + warp;
            project_impl<51>(emb3, W3, b3, g_list3, g_cnt[0], all_f,
                             wid, NB51 * 8);
        } else {
            int wid = (blockIdx.x - NB51) * 8 + warp;
            project_impl<102>(emb4, W4, b4, g_list4, g_cnt[1], all_f,
                              wid, (NBUILD - NB51) * 8);
        }
    } else {
        copy_impl(bucket, e0, e1, e2, (float4*)all_f, rows,
                  blockIdx.x - NBUILD);
    }
}

// 8-thread group handles EIGHT tokens (MLP=8). Resets counters for replay.
__global__ void gather_kernel(const int4*   __restrict__ x4,
                              const float4* __restrict__ tab,
                              float4*       __restrict__ out,
                              int Tg)
{
    if (blockIdx.x == 0 && threadIdx.x == 0) {
        g_cnt[0] = 0; g_cnt[1] = 0; g_build_done = 0;
    }

    int gid = blockIdx.x * blockDim.x + threadIdx.x;
    int grp = gid >> 3;
    if (grp >= Tg) return;
    int c = gid & 7;

    int4 ia = __ldg(&x4[(size_t)grp * 2 + 0]);
    int4 ib = __ldg(&x4[(size_t)grp * 2 + 1]);

    float4 v0 = __ldg(&tab[(size_t)ia.x * 8 + c]);
    float4 v1 = __ldg(&tab[(size_t)ia.y * 8 + c]);
    float4 v2 = __ldg(&tab[(size_t)ia.z * 8 + c]);
    float4 v3 = __ldg(&tab[(size_t)ia.w * 8 + c]);
    float4 v4 = __ldg(&tab[(size_t)ib.x * 8 + c]);
    float4 v5 = __ldg(&tab[(size_t)ib.y * 8 + c]);
    float4 v6 = __ldg(&tab[(size_t)ib.z * 8 + c]);
    float4 v7 = __ldg(&tab[(size_t)ib.w * 8 + c]);

    size_t base = (size_t)grp * 64 + c;
    __stcs(&out[base +  0], v0);
    __stcs(&out[base +  8], v1);
    __stcs(&out[base + 16], v2);
    __stcs(&out[base + 24], v3);
    __stcs(&out[base + 32], v4);
    __stcs(&out[base + 40], v5);
    __stcs(&out[base + 48], v6);
    __stcs(&out[base + 56], v7);
}

extern "C" void kernel_launch(void* const* d_in, const int* in_sizes, int n_in,
                              void* d_out, int out_size)
{
    const int*   x      = (const int*)  d_in[0];
    const int*   bucket = (const int*)  d_in[1];
    const float* emb0   = (const float*)d_in[2];
    const float* emb1   = (const float*)d_in[3];
    const float* emb2   = (const float*)d_in[4];
    const float* emb3   = (const float*)d_in[5];
    const float* emb4   = (const float*)d_in[6];
    const float* W3     = (const float*)d_in[7];
    const float* b3     = (const float*)d_in[8];
    const float* W4     = (const float*)d_in[9];
    const float* b4     = (const float*)d_in[10];

    const int T    = in_sizes[0];          // 1,048,576 tokens (multiple of 8)
    const int rows = in_sizes[1];          // 100,000

    float* all_f;
    cudaGetSymbolAddress((void**)&all_f, g_all);

    const int NBCOPY = (rows * 8 + 255) / 256;     // 3125
    stage_b<<<NBUILD + NBCOPY, 256>>>(
        bucket, (const float4*)emb0, (const float4*)emb1, (const float4*)emb2,
        emb3, W3, b3, emb4, W4, b4, all_f, rows);

    const int Tg = T / 8;
    long long gthreads_total = (long long)Tg * 8;
    int gblocks = (int)((gthreads_total + 255) / 256);
    gather_kernel<<<gblocks, 256>>>((const int4*)x, (const float4*)all_f,
                                    (float4*)d_out, Tg);
}